// round 2
// baseline (speedup 1.0000x reference)
#include <cuda_runtime.h>
#include <cstdint>

#define BB   16
#define HH   320
#define WW   1024
#define HWW  (HH * WW)
#define NN   16384
#define NT   80
#define TILEE 4096
#define NWORDS (HWW / 32)
#define MAXD 40.0f
#define NBUK 8192
#define BUKSHIFT 19

__device__ uint32_t g_perm[HWW];
__device__ uint32_t g_v1[HWW];
__device__ unsigned long long g_buf[HWW];
__device__ uint32_t g_pay[HWW];
__device__ int g_hist1[NBUK], g_hist2[NBUK];
__device__ int g_bstart1[NBUK + 1], g_bstart2[NBUK + 1];
__device__ int g_cur1[NBUK], g_cur2[NBUK];

__device__ uint32_t g_bm[BB * NWORDS];
__device__ int      g_tileCnt[BB * NT];
__device__ int      g_tileOff[BB * NT];
__device__ int      g_validNum[BB];
__device__ int      g_validPix[BB * NN];

__host__ __device__ __forceinline__ void tf2x32(uint32_t k0, uint32_t k1,
                                                uint32_t x0, uint32_t x1,
                                                uint32_t& o0, uint32_t& o1) {
    uint32_t ks0 = k0, ks1 = k1, ks2 = 0x1BD11BDAu ^ k0 ^ k1;
    x0 += ks0; x1 += ks1;
    #define TFMIX(r) { x0 += x1; x1 = (x1 << (r)) | (x1 >> (32 - (r))); x1 ^= x0; }
    TFMIX(13) TFMIX(15) TFMIX(26) TFMIX(6)  x0 += ks1; x1 += ks2 + 1u;
    TFMIX(17) TFMIX(29) TFMIX(16) TFMIX(24) x0 += ks2; x1 += ks0 + 2u;
    TFMIX(13) TFMIX(15) TFMIX(26) TFMIX(6)  x0 += ks0; x1 += ks1 + 3u;
    TFMIX(17) TFMIX(29) TFMIX(16) TFMIX(24) x0 += ks1; x1 += ks2 + 4u;
    TFMIX(13) TFMIX(15) TFMIX(26) TFMIX(6)  x0 += ks2; x1 += ks0 + 5u;
    #undef TFMIX
    o0 = x0; o1 = x1;
}

__device__ __forceinline__ uint32_t rbits(uint32_t k0, uint32_t k1, uint32_t i) {
    uint32_t a, b;
    tf2x32(k0, k1, 0u, i, a, b);
    return a ^ b;
}

__global__ void k_zero() {
    int i = blockIdx.x * 256 + threadIdx.x;
    if (i < NBUK) { g_hist1[i] = 0; g_hist2[i] = 0; }
}

__global__ void k_hist(uint32_t k0, uint32_t k1, int round) {
    uint32_t i = blockIdx.x * 512 + threadIdx.x;
    uint32_t key = rbits(k0, k1, i);
    int* hist = (round == 1) ? g_hist1 : g_hist2;
    atomicAdd(&hist[key >> BUKSHIFT], 1);
}

__global__ void k_scanb(int round) {
    __shared__ int part[1024];
    const int* hist = (round == 1) ? g_hist1 : g_hist2;
    int* bstart = (round == 1) ? g_bstart1 : g_bstart2;
    int* cursor = (round == 1) ? g_cur1 : g_cur2;
    int t = threadIdx.x;
    int local[8];
    int s = 0;
#pragma unroll
    for (int i = 0; i < 8; i++) { local[i] = s; s += hist[t * 8 + i]; }
    part[t] = s;
    __syncthreads();
    for (int off = 1; off < 1024; off <<= 1) {
        int u = (t >= off) ? part[t - off] : 0;
        __syncthreads();
        part[t] += u;
        __syncthreads();
    }
    int excl = part[t] - s;
#pragma unroll
    for (int i = 0; i < 8; i++) {
        int v = excl + local[i];
        bstart[t * 8 + i] = v;
        cursor[t * 8 + i] = v;
    }
    if (t == 1023) bstart[NBUK] = part[1023];
}

__global__ void k_place(uint32_t k0, uint32_t k1, int round) {
    uint32_t i = blockIdx.x * 512 + threadIdx.x;
    uint32_t key = rbits(k0, k1, i);
    int* cursor = (round == 1) ? g_cur1 : g_cur2;
    int pos = atomicAdd(&cursor[key >> BUKSHIFT], 1);
    g_buf[pos] = ((unsigned long long)key << BUKSHIFT) | (unsigned long long)i;
    g_pay[pos] = (round == 1) ? i : g_v1[i];
}

__global__ void k_bsort(int round) {
    const int* bstart = (round == 1) ? g_bstart1 : g_bstart2;
    uint32_t* outv = (round == 1) ? g_v1 : g_perm;
    int buk = blockIdx.x * 8 + (threadIdx.x >> 5);
    int lane = threadIdx.x & 31;
    int start = bstart[buk];
    int m = bstart[buk + 1] - start;
    for (int e = lane; e < m; e += 32) {
        unsigned long long ke = g_buf[start + e];
        int rank = 0;
        for (int i = 0; i < m; i++)
            rank += (g_buf[start + i] < ke) ? 1 : 0;
        outv[start + rank] = g_pay[start + e];
    }
}

__global__ void k_bitmask(const float* __restrict__ depth) {
    int b = blockIdx.y;
    int base = blockIdx.x * 2048;
    int lane = threadIdx.x & 31;
    const float* dp = depth + (size_t)b * HWW;
#pragma unroll
    for (int it = 0; it < 8; it++) {
        int p = base + it * 256 + threadIdx.x;
        float d = dp[p];
        unsigned bal = __ballot_sync(0xffffffffu, d < MAXD);
        if (lane == 0) g_bm[b * NWORDS + (p >> 5)] = bal;
    }
}

__global__ void k_count() {
    __shared__ uint32_t bm[NWORDS];
    __shared__ int sc[4];
    int b = blockIdx.y;
    for (int i = threadIdx.x; i < NWORDS; i += 256) bm[i] = g_bm[b * NWORDS + i];
    if (threadIdx.x < 4) sc[threadIdx.x] = 0;
    __syncthreads();
    int chunk = blockIdx.x * 16384;
    int cnt[4] = {0, 0, 0, 0};
#pragma unroll
    for (int k = 0; k < 64; k++) {
        int j = chunk + k * 256 + threadIdx.x;
        uint32_t p = g_perm[j];
        cnt[k >> 4] += (int)((bm[p >> 5] >> (p & 31)) & 1u);
    }
#pragma unroll
    for (int q = 0; q < 4; q++) atomicAdd(&sc[q], cnt[q]);
    __syncthreads();
    if (threadIdx.x < 4)
        g_tileCnt[b * NT + blockIdx.x * 4 + threadIdx.x] = sc[threadIdx.x];
}

__global__ void k_scan() {
    __shared__ int s[NT];
    int b = blockIdx.x;
    if (threadIdx.x < NT) s[threadIdx.x] = g_tileCnt[b * NT + threadIdx.x];
    __syncthreads();
    if (threadIdx.x == 0) {
        int run = 0;
        for (int t = 0; t < NT; t++) { int c = s[t]; s[t] = run; run += c; }
        g_validNum[b] = run;
    }
    __syncthreads();
    if (threadIdx.x < NT) g_tileOff[b * NT + threadIdx.x] = s[threadIdx.x];
}

__global__ void k_scatter(const float* __restrict__ depth) {
    int b = blockIdx.y, t = blockIdx.x;
    int off = g_tileOff[b * NT + t];
    if (off >= NN) return;
    __shared__ int sW[8];
    const float* dp = depth + (size_t)b * HWW;
    int lane = threadIdx.x & 31, wid = threadIdx.x >> 5;
    unsigned lmask = (1u << lane) - 1u;
    int running = 0;
    int base = t * TILEE;
    for (int k = 0; k < 16; k++) {
        int j = base + k * 256 + threadIdx.x;
        uint32_t p = g_perm[j];
        bool valid = __ldg(&dp[p]) < MAXD;
        unsigned bal = __ballot_sync(0xffffffffu, valid);
        if (lane == 0) sW[wid] = __popc(bal);
        __syncthreads();
        int wp = 0, tot = 0;
#pragma unroll
        for (int w = 0; w < 8; w++) { int c = sW[w]; tot += c; wp += (w < wid) ? c : 0; }
        if (valid) {
            int g = off + running + wp + __popc(bal & lmask);
            if (g < NN) g_validPix[b * NN + g] = (int)p;
        }
        running += tot;
        __syncthreads();
    }
}

__global__ void k_output(const float* __restrict__ depth, const float* __restrict__ invK,
                         const float* __restrict__ bind, float* __restrict__ out) {
    int b = blockIdx.y;
    int n = blockIdx.x * 256 + threadIdx.x;
    float bv = bind[b * NN + n];
    float vnf = (float)g_validNum[b];
    int li = (vnf > 0.0f) ? (int)fmodf(bv, vnf) : 0;
    int p = g_validPix[b * NN + li];
    float d = __ldg(&depth[(size_t)b * HWW + p]);
    float xf = (float)(p & (WW - 1));
    float yf = (float)(p >> 10);
    float px = xf * d, py = yf * d;
    const float* Km = invK + b * 16;
#pragma unroll
    for (int c = 0; c < 3; c++) {
        float v = fmaf(__ldg(&Km[c * 4 + 0]), px,
                  fmaf(__ldg(&Km[c * 4 + 1]), py,
                  fmaf(__ldg(&Km[c * 4 + 2]), d, __ldg(&Km[c * 4 + 3]))));
        out[((size_t)b * 3 + c) * NN + n] = v;
    }
}

extern "C" void kernel_launch(void* const* d_in, const int* in_sizes, int n_in,
                              void* d_out, int out_size) {
    const float* depth = (const float*)d_in[0];
    const float* invK  = (const float*)d_in[1];
    const float* bind  = (const float*)d_in[3];
    float* out = (float*)d_out;

    // Host-side scalar key schedule (pure CPU math; values baked into graph).
    uint32_t k0 = 0u, k1 = 42u;
    uint32_t sk[2][2];
    for (int r = 0; r < 2; r++) {
        uint32_t nk0, nk1, s0, s1;
        tf2x32(k0, k1, 0u, 0u, nk0, nk1);
        tf2x32(k0, k1, 0u, 1u, s0, s1);
        k0 = nk0; k1 = nk1;
        sk[r][0] = s0; sk[r][1] = s1;
    }

    k_zero<<<(NBUK + 255) / 256, 256>>>();

    k_hist <<<HWW / 512, 512>>>(sk[0][0], sk[0][1], 1);
    k_scanb<<<1, 1024>>>(1);
    k_place<<<HWW / 512, 512>>>(sk[0][0], sk[0][1], 1);
    k_bsort<<<NBUK / 8, 256>>>(1);

    k_hist <<<HWW / 512, 512>>>(sk[1][0], sk[1][1], 2);
    k_scanb<<<1, 1024>>>(2);
    k_place<<<HWW / 512, 512>>>(sk[1][0], sk[1][1], 2);
    k_bsort<<<NBUK / 8, 256>>>(2);

    k_bitmask<<<dim3(160, BB), 256>>>(depth);
    k_count  <<<dim3(20, BB), 256>>>();
    k_scan   <<<BB, 128>>>();
    k_scatter<<<dim3(NT, BB), 256>>>(depth);
    k_output <<<dim3(NN / 256, BB), 256>>>(depth, invK, bind, out);
}